// round 1
// baseline (speedup 1.0000x reference)
#include <cuda_runtime.h>
#include <cuda_bf16.h>
#include <cstdint>

// Grouped conv2d: x[16,256,128,128] * W[512,16,3,3] (groups=16) + b -> out[16,512,128,128]
// fp32 direct conv, smem-tiled.
// Tile: one (n, group) pair, 16(h) x 32(w) spatial tile, all 32 couts of the group.
// Thread: 2(h) x 4(w) pixels x 8 couts = 64 accumulators.

#define THREADS 256

// smem: x tile [ci=16][rows=18][cols padded to 40]  (halo of 1 on each side, 34 used)
//       w tile [ci*9=144][cout=32]  (repacked so cout is contiguous -> float4 loads)
#define SX_CI_STRIDE (18 * 40)      // 720 floats per ci plane
#define SX_FLOATS (16 * 18 * 40)    // 11520
#define SW_FLOATS (144 * 32)        // 4608
#define SMEM_BYTES ((SX_FLOATS + SW_FLOATS) * 4)   // 64512 B

__global__ __launch_bounds__(THREADS, 2)
void grouped_conv_kernel(const float* __restrict__ x,
                         const float* __restrict__ w,
                         const float* __restrict__ b,
                         float* __restrict__ out)
{
    extern __shared__ float sm[];
    float* sx = sm;                 // 11520 floats
    float* sw = sm + SX_FLOATS;     // 4608 floats

    const int wt = blockIdx.x;          // 0..3   (w tiles of 32)
    const int ht = blockIdx.y;          // 0..7   (h tiles of 16)
    const int ng = blockIdx.z;          // 0..255 (n*16 + g)
    const int n  = ng >> 4;
    const int g  = ng & 15;
    const int h0 = ht * 16;
    const int w0 = wt * 32;
    const int tid = threadIdx.x;

    // ---- load x tile (16 ci x 18 rows x 34 cols, zero-padded halo) ----
    const float* xg = x + ((size_t)(n * 256 + g * 16) * (128 * 128));
    for (int idx = tid; idx < 16 * 18 * 34; idx += THREADS) {
        int c  = idx % 34;
        int t  = idx / 34;
        int r  = t % 18;
        int ci = t / 18;
        int gh = h0 - 1 + r;
        int gw = w0 - 1 + c;
        float v = 0.0f;
        if ((unsigned)gh < 128u && (unsigned)gw < 128u)
            v = xg[ci * 16384 + gh * 128 + gw];
        sx[ci * SX_CI_STRIDE + r * 40 + c] = v;
    }

    // ---- load + repack weights: global W[g*32+co][ci][kh][kw] -> sw[(ci*9+kp)*32 + co] ----
    const float* wg = w + (size_t)(g * 32) * 144;
    for (int idx = tid; idx < 32 * 144; idx += THREADS) {
        int co  = idx / 144;
        int rem = idx % 144;            // ci*9 + kh*3 + kw
        sw[rem * 32 + co] = wg[idx];
    }
    __syncthreads();

    // ---- thread -> (cout group, w subtile, h subtile) ----
    const int cgrp = tid & 3;           // 4 groups of 8 couts
    const int wsub = (tid >> 2) & 7;    // 8 subtiles of 4 w
    const int hsub = tid >> 5;          // 8 subtiles of 2 h
    const int lh0 = hsub * 2;
    const int lw0 = wsub * 4;
    const int co0 = cgrp * 8;

    float acc[8][8];                    // [co][ph*4+pw]
    #pragma unroll
    for (int i = 0; i < 8; ++i)
        #pragma unroll
        for (int j = 0; j < 8; ++j) acc[i][j] = 0.0f;

    for (int ci = 0; ci < 16; ++ci) {
        // x register cache: 4 rows (lh0 .. lh0+3) x 8 cols (lw0 .. lw0+7), float4 loads
        float xr[4][8];
        #pragma unroll
        for (int r = 0; r < 4; ++r) {
            const float4* p = (const float4*)(sx + ci * SX_CI_STRIDE + (lh0 + r) * 40 + lw0);
            float4 a = p[0];
            float4 c = p[1];
            xr[r][0] = a.x; xr[r][1] = a.y; xr[r][2] = a.z; xr[r][3] = a.w;
            xr[r][4] = c.x; xr[r][5] = c.y; xr[r][6] = c.z; xr[r][7] = c.w;
        }
        #pragma unroll
        for (int kp = 0; kp < 9; ++kp) {
            const int kh = kp / 3;
            const int kw = kp % 3;
            const float4* wp = (const float4*)(sw + (ci * 9 + kp) * 32 + co0);
            float4 wa = wp[0];
            float4 wb = wp[1];
            float wv[8] = {wa.x, wa.y, wa.z, wa.w, wb.x, wb.y, wb.z, wb.w};
            #pragma unroll
            for (int ph = 0; ph < 2; ++ph) {
                #pragma unroll
                for (int pw = 0; pw < 4; ++pw) {
                    float xv = xr[ph + kh][pw + kw];
                    #pragma unroll
                    for (int co = 0; co < 8; ++co)
                        acc[co][ph * 4 + pw] = fmaf(xv, wv[co], acc[co][ph * 4 + pw]);
                }
            }
        }
    }

    // ---- epilogue: bias + store (float4, coalesced in w) ----
    const int gco0 = g * 32 + co0;
    float bias[8];
    #pragma unroll
    for (int co = 0; co < 8; ++co) bias[co] = __ldg(&b[gco0 + co]);

    float* og = out + ((size_t)(n * 512 + gco0) * 16384);
    #pragma unroll
    for (int co = 0; co < 8; ++co) {
        #pragma unroll
        for (int ph = 0; ph < 2; ++ph) {
            float4 v;
            v.x = acc[co][ph * 4 + 0] + bias[co];
            v.y = acc[co][ph * 4 + 1] + bias[co];
            v.z = acc[co][ph * 4 + 2] + bias[co];
            v.w = acc[co][ph * 4 + 3] + bias[co];
            *(float4*)(og + (size_t)co * 16384 + (h0 + lh0 + ph) * 128 + (w0 + lw0)) = v;
        }
    }
}

extern "C" void kernel_launch(void* const* d_in, const int* in_sizes, int n_in,
                              void* d_out, int out_size)
{
    const float* x = (const float*)d_in[0];
    const float* w = (const float*)d_in[1];
    const float* b = (const float*)d_in[2];
    float* out = (float*)d_out;

    cudaFuncSetAttribute(grouped_conv_kernel,
                         cudaFuncAttributeMaxDynamicSharedMemorySize, SMEM_BYTES);

    dim3 grid(4, 8, 256);   // w tiles, h tiles, n*16+g
    grouped_conv_kernel<<<grid, THREADS, SMEM_BYTES>>>(x, w, b, out);
}

// round 2
// speedup vs baseline: 1.0455x; 1.0455x over previous
#include <cuda_runtime.h>
#include <cuda_bf16.h>
#include <cstdint>

// Grouped conv2d: x[16,256,128,128] * W[512,16,3,3] (groups=16) + b -> out[16,512,128,128]
// fp32 direct conv, smem-tiled, f32x2 packed FMA (FFMA2) over cout pairs.
// Tile: one (n, group) pair, 16(h) x 32(w) spatial tile, all 32 couts of the group.
// Thread: 2(h) x 4(w) pixels x 8 couts (= 4 co-pairs) = 32 packed accumulators.

#define THREADS 256

#define SX_CI_STRIDE (18 * 40)      // 720 floats per ci plane
#define SX_FLOATS (16 * 18 * 40)    // 11520
#define SW_FLOATS (144 * 32)        // 4608
#define SMEM_BYTES ((SX_FLOATS + SW_FLOATS) * 4)   // 64512 B

typedef unsigned long long ull;

__device__ __forceinline__ ull bcast2(float v) {
    ull r;
    asm("mov.b64 %0, {%1, %1};" : "=l"(r) : "f"(v));
    return r;
}
__device__ __forceinline__ ull pack2(float lo, float hi) {
    ull r;
    asm("mov.b64 %0, {%1, %2};" : "=l"(r) : "f"(lo), "f"(hi));
    return r;
}
__device__ __forceinline__ void unpack2(ull v, float& lo, float& hi) {
    asm("mov.b64 {%0, %1}, %2;" : "=f"(lo), "=f"(hi) : "l"(v));
}
__device__ __forceinline__ ull fma2(ull a, ull b, ull c) {
    ull d;
    asm("fma.rn.f32x2 %0, %1, %2, %3;" : "=l"(d) : "l"(a), "l"(b), "l"(c));
    return d;
}
__device__ __forceinline__ ull add2(ull a, ull b) {
    ull d;
    asm("add.rn.f32x2 %0, %1, %2;" : "=l"(d) : "l"(a), "l"(b));
    return d;
}

__global__ __launch_bounds__(THREADS, 2)
void grouped_conv_kernel(const float* __restrict__ x,
                         const float* __restrict__ w,
                         const float* __restrict__ b,
                         float* __restrict__ out)
{
    extern __shared__ float sm[];
    float* sx = sm;                 // 11520 floats
    float* sw = sm + SX_FLOATS;     // 4608 floats

    const int wt = blockIdx.x;          // 0..3   (w tiles of 32)
    const int ht = blockIdx.y;          // 0..7   (h tiles of 16)
    const int ng = blockIdx.z;          // 0..255 (n*16 + g)
    const int n  = ng >> 4;
    const int g  = ng & 15;
    const int h0 = ht * 16;
    const int w0 = wt * 32;
    const int tid = threadIdx.x;

    // ---- load x tile (16 ci x 18 rows x 34 cols, zero-padded halo) ----
    const float* xg = x + ((size_t)(n * 256 + g * 16) * (128 * 128));
    for (int idx = tid; idx < 16 * 18 * 34; idx += THREADS) {
        int c  = idx % 34;
        int t  = idx / 34;
        int r  = t % 18;
        int ci = t / 18;
        int gh = h0 - 1 + r;
        int gw = w0 - 1 + c;
        float v = 0.0f;
        if ((unsigned)gh < 128u && (unsigned)gw < 128u)
            v = xg[ci * 16384 + gh * 128 + gw];
        sx[ci * SX_CI_STRIDE + r * 40 + c] = v;
    }

    // ---- load + repack weights: global W[g*32+co][ci][kh][kw] -> sw[(ci*9+kp)*32 + co] ----
    const float* wg = w + (size_t)(g * 32) * 144;
    for (int idx = tid; idx < 32 * 144; idx += THREADS) {
        int co  = idx / 144;
        int rem = idx % 144;            // ci*9 + kh*3 + kw
        sw[rem * 32 + co] = wg[idx];
    }
    __syncthreads();

    // ---- thread -> (cout group, w subtile, h subtile) ----
    const int cgrp = tid & 3;           // 4 groups of 8 couts
    const int wsub = (tid >> 2) & 7;    // 8 subtiles of 4 w
    const int hsub = tid >> 5;          // 8 subtiles of 2 h
    const int lh0 = hsub * 2;
    const int lw0 = wsub * 4;
    const int co0 = cgrp * 8;

    const uint32_t sw_base = (uint32_t)__cvta_generic_to_shared(sw) + co0 * 4;

    // acc2[pair][px] : pair p covers couts (co0+2p, co0+2p+1); px = ph*4+pw
    ull acc2[4][8];
    #pragma unroll
    for (int p = 0; p < 4; ++p)
        #pragma unroll
        for (int j = 0; j < 8; ++j) acc2[p][j] = 0ull;

    for (int ci = 0; ci < 16; ++ci) {
        // x register cache: 4 rows x 8 cols (only 6 cols used), then broadcast-pack 4x6
        ull x2[4][6];
        #pragma unroll
        for (int r = 0; r < 4; ++r) {
            const float4* p = (const float4*)(sx + ci * SX_CI_STRIDE + (lh0 + r) * 40 + lw0);
            float4 a = p[0];
            float4 c = p[1];
            x2[r][0] = bcast2(a.x);
            x2[r][1] = bcast2(a.y);
            x2[r][2] = bcast2(a.z);
            x2[r][3] = bcast2(a.w);
            x2[r][4] = bcast2(c.x);
            x2[r][5] = bcast2(c.y);
        }
        #pragma unroll
        for (int kp = 0; kp < 9; ++kp) {
            const int kh = kp / 3;
            const int kw = kp % 3;
            ull w01, w23, w45, w67;
            {
                uint32_t a0 = sw_base + (ci * 9 + kp) * 128;   // 32 floats * 4B
                asm("ld.shared.v2.u64 {%0, %1}, [%2];" : "=l"(w01), "=l"(w23) : "r"(a0));
                asm("ld.shared.v2.u64 {%0, %1}, [%2];" : "=l"(w45), "=l"(w67) : "r"(a0 + 16));
            }
            #pragma unroll
            for (int ph = 0; ph < 2; ++ph) {
                #pragma unroll
                for (int pw = 0; pw < 4; ++pw) {
                    ull xx = x2[ph + kh][pw + kw];
                    const int px = ph * 4 + pw;
                    acc2[0][px] = fma2(xx, w01, acc2[0][px]);
                    acc2[1][px] = fma2(xx, w23, acc2[1][px]);
                    acc2[2][px] = fma2(xx, w45, acc2[2][px]);
                    acc2[3][px] = fma2(xx, w67, acc2[3][px]);
                }
            }
        }
    }

    // ---- epilogue: bias (packed) + unpack + store (float4, coalesced in w) ----
    const int gco0 = g * 32 + co0;
    ull b2[4];
    #pragma unroll
    for (int p = 0; p < 4; ++p)
        b2[p] = pack2(__ldg(&b[gco0 + 2 * p]), __ldg(&b[gco0 + 2 * p + 1]));

    #pragma unroll
    for (int p = 0; p < 4; ++p)
        #pragma unroll
        for (int j = 0; j < 8; ++j) acc2[p][j] = add2(acc2[p][j], b2[p]);

    float* og = out + ((size_t)(n * 512 + gco0) * 16384);
    #pragma unroll
    for (int p = 0; p < 4; ++p) {
        #pragma unroll
        for (int ph = 0; ph < 2; ++ph) {
            float lo0, hi0, lo1, hi1, lo2, hi2, lo3, hi3;
            unpack2(acc2[p][ph * 4 + 0], lo0, hi0);
            unpack2(acc2[p][ph * 4 + 1], lo1, hi1);
            unpack2(acc2[p][ph * 4 + 2], lo2, hi2);
            unpack2(acc2[p][ph * 4 + 3], lo3, hi3);
            float4 vlo = make_float4(lo0, lo1, lo2, lo3);
            float4 vhi = make_float4(hi0, hi1, hi2, hi3);
            size_t row = (size_t)(h0 + lh0 + ph) * 128 + (w0 + lw0);
            *(float4*)(og + (size_t)(2 * p)     * 16384 + row) = vlo;
            *(float4*)(og + (size_t)(2 * p + 1) * 16384 + row) = vhi;
        }
    }
}

extern "C" void kernel_launch(void* const* d_in, const int* in_sizes, int n_in,
                              void* d_out, int out_size)
{
    const float* x = (const float*)d_in[0];
    const float* w = (const float*)d_in[1];
    const float* b = (const float*)d_in[2];
    float* out = (float*)d_out;

    cudaFuncSetAttribute(grouped_conv_kernel,
                         cudaFuncAttributeMaxDynamicSharedMemorySize, SMEM_BYTES);

    dim3 grid(4, 8, 256);   // w tiles, h tiles, n*16+g
    grouped_conv_kernel<<<grid, THREADS, SMEM_BYTES>>>(x, w, b, out);
}

// round 4
// speedup vs baseline: 1.6395x; 1.5681x over previous
#include <cuda_runtime.h>
#include <cuda_bf16.h>
#include <cstdint>

// Grouped conv2d via implicit GEMM on mma.sync (HMMA, base sm_103 target),
// split-bf16 3-pass for fp32-grade accuracy.
// x[16,256,128,128] * W[512,16,3,3] (groups=16) + b -> out[16,512,128,128]
//
// Per (n,g): D[pixels,32co] = sum_{tap} A_tap[px,16ci] x B_tap[16ci,32co]
// mma.sync.aligned.m16n8k16.row.col.f32.bf16.bf16.f32, acc fp32 in registers.
// Passes: Ahi*Bhi + Ahi*Blo + Alo*Bhi (xl*wl ~2^-16 dropped).
//
// CTA: (n,g, 4 h-rows). 8 warps: warp = (row = wid>>1, half = wid&1).
// Warp tile: 16 px x 32 co per segment, 4 segments of 16px over its 64-w half.

#define THREADS 256

// ---- smem layout (bytes) ----
// B fragments: [combo=tap*2+hl (18)][lane (32)][12 u32 (48B, 8 used)]
#define SWF_OFF   0
#define SWF_BYTES (18 * 32 * 48)            // 27648
// x planes hi/lo: [row 0..5][col 0..129][ci 0..15 bf16], col stride 36B
#define XCOL_STRIDE 36
#define XROW_STRIDE (130 * XCOL_STRIDE)     // 4680
#define XPLANE_BYTES (6 * XROW_STRIDE)      // 28080
#define SXH_OFF   SWF_BYTES                 // 27648
#define SXL_OFF   (SXH_OFF + XPLANE_BYTES)  // 55728
#define SBIAS_OFF (SXL_OFF + XPLANE_BYTES)  // 83808
#define SMEM_TOTAL (SBIAS_OFF + 128)        // 83936

__device__ __forceinline__ void mma16816(float& c0, float& c1, float& c2, float& c3,
                                         uint32_t a0, uint32_t a1, uint32_t a2, uint32_t a3,
                                         uint32_t b0, uint32_t b1) {
    asm volatile("mma.sync.aligned.m16n8k16.row.col.f32.bf16.bf16.f32 "
                 "{%0,%1,%2,%3}, {%4,%5,%6,%7}, {%8,%9}, {%0,%1,%2,%3};"
                 : "+f"(c0), "+f"(c1), "+f"(c2), "+f"(c3)
                 : "r"(a0), "r"(a1), "r"(a2), "r"(a3), "r"(b0), "r"(b1));
}

__device__ __forceinline__ uint32_t bf16_hi_lo_pack(float v0, float v1, int want_lo) {
    __nv_bfloat16 h0 = __float2bfloat16(v0);
    __nv_bfloat16 h1 = __float2bfloat16(v1);
    __nv_bfloat16 e0, e1;
    if (want_lo) {
        e0 = __float2bfloat16(v0 - __bfloat162float(h0));
        e1 = __float2bfloat16(v1 - __bfloat162float(h1));
    } else {
        e0 = h0; e1 = h1;
    }
    return (uint32_t)__bfloat16_as_ushort(e0) | ((uint32_t)__bfloat16_as_ushort(e1) << 16);
}

__global__ __launch_bounds__(THREADS, 2)
void grouped_conv_hmma(const float* __restrict__ x,
                       const float* __restrict__ w,
                       const float* __restrict__ bias,
                       float* __restrict__ out)
{
    extern __shared__ char smem[];
    uint32_t* swf = (uint32_t*)(smem + SWF_OFF);
    char* sxh = smem + SXH_OFF;
    char* sxl = smem + SXL_OFF;
    float* sbias = (float*)(smem + SBIAS_OFF);

    const int tid = threadIdx.x;
    const int wid = tid >> 5;
    const int lane = tid & 31;

    const int hb = blockIdx.x;          // 0..31  (4-row blocks)
    const int ng = blockIdx.y;          // 0..255
    const int n  = ng >> 4;
    const int g  = ng & 15;
    const int h0 = hb * 4;

    // ---- stage x: rows h0-1..h0+4, cols -1..128, split bf16 hi/lo ----
    const float* xg = x + (size_t)(n * 256 + g * 16) * 16384;
    for (int idx = tid; idx < 6 * 16 * 130; idx += THREADS) {
        int c  = idx % 130;
        int t  = idx / 130;
        int ci = t % 16;
        int r  = t / 16;                // 0..5
        int gh = h0 - 1 + r;
        int gw = c - 1;
        float v = 0.0f;
        if ((unsigned)gh < 128u && (unsigned)gw < 128u)
            v = xg[ci * 16384 + gh * 128 + gw];
        __nv_bfloat16 hbv = __float2bfloat16(v);
        __nv_bfloat16 lbv = __float2bfloat16(v - __bfloat162float(hbv));
        uint32_t off = (uint32_t)(r * XROW_STRIDE + c * XCOL_STRIDE + ci * 2);
        *(__nv_bfloat16*)(sxh + off) = hbv;
        *(__nv_bfloat16*)(sxl + off) = lbv;
    }

    // ---- stage W as ready-made B fragments ----
    // combo = tap*2 + hl; lane (g4=lane>>2 -> co within n8, t4=lane&3 -> k pair)
    // slot = nt*2 + r : u32 = { W[nt*8+g4][2*t4+8r + 0/1][tap] } (hl part)
    const float* wgp = w + (size_t)(g * 32) * 144;
    for (int idx = tid; idx < 18 * 32 * 8; idx += THREADS) {
        int slot  = idx & 7;
        int lane2 = (idx >> 3) & 31;
        int combo = idx >> 8;           // 0..17
        int tap = combo >> 1, hl = combo & 1;
        int g4 = lane2 >> 2, t4 = lane2 & 3;
        int nt = slot >> 1, rr = slot & 1;
        int co  = nt * 8 + g4;
        int ci0 = 2 * t4 + 8 * rr;
        float v0 = wgp[co * 144 + ci0 * 9 + tap];
        float v1 = wgp[co * 144 + (ci0 + 1) * 9 + tap];
        swf[(combo * 32 + lane2) * 12 + slot] = bf16_hi_lo_pack(v0, v1, hl);
    }
    if (tid < 32) sbias[tid] = bias[g * 32 + tid];
    __syncthreads();

    // ---- main: warp = (row, w-half); 4 segments of 16 px ----
    const int wrow  = wid >> 1;          // 0..3
    const int whalf = (wid & 1) * 64;
    const int g4 = lane >> 2, t4 = lane & 3;
    const int h = h0 + wrow;
    float* og = out + (size_t)(n * 512 + g * 32) * 16384 + (size_t)h * 128;

    float bias_lo[4], bias_hi[4];
    #pragma unroll
    for (int nt = 0; nt < 4; ++nt) {
        bias_lo[nt] = sbias[nt * 8 + 2 * t4];
        bias_hi[nt] = sbias[nt * 8 + 2 * t4 + 1];
    }

    for (int seg = 0; seg < 4; ++seg) {
        const int w0 = whalf + seg * 16;
        float acc[4][4];
        #pragma unroll
        for (int nt = 0; nt < 4; ++nt)
            #pragma unroll
            for (int i = 0; i < 4; ++i) acc[nt][i] = 0.0f;

        #pragma unroll
        for (int tap = 0; tap < 9; ++tap) {
            const int dh = tap / 3, dw = tap % 3;
            // B fragments (hi, lo): 2x LDS.128 each, lane-major layout
            uint4 bh0 = *(const uint4*)(swf + ((tap * 2 + 0) * 32 + lane) * 12);
            uint4 bh1 = *(const uint4*)(swf + ((tap * 2 + 0) * 32 + lane) * 12 + 4);
            uint4 bl0 = *(const uint4*)(swf + ((tap * 2 + 1) * 32 + lane) * 12);
            uint4 bl1 = *(const uint4*)(swf + ((tap * 2 + 1) * 32 + lane) * 12 + 4);
            // A fragments (hi, lo)
            const uint32_t abase = (uint32_t)((wrow + dh) * XROW_STRIDE
                                            + (w0 + dw) * XCOL_STRIDE + t4 * 4);
            uint32_t ah0 = *(const uint32_t*)(sxh + abase + g4 * XCOL_STRIDE);
            uint32_t ah1 = *(const uint32_t*)(sxh + abase + (g4 + 8) * XCOL_STRIDE);
            uint32_t ah2 = *(const uint32_t*)(sxh + abase + g4 * XCOL_STRIDE + 16);
            uint32_t ah3 = *(const uint32_t*)(sxh + abase + (g4 + 8) * XCOL_STRIDE + 16);
            uint32_t al0 = *(const uint32_t*)(sxl + abase + g4 * XCOL_STRIDE);
            uint32_t al1 = *(const uint32_t*)(sxl + abase + (g4 + 8) * XCOL_STRIDE);
            uint32_t al2 = *(const uint32_t*)(sxl + abase + g4 * XCOL_STRIDE + 16);
            uint32_t al3 = *(const uint32_t*)(sxl + abase + (g4 + 8) * XCOL_STRIDE + 16);

            // nt 0: regs bh0.x/y  nt1: bh0.z/w  nt2: bh1.x/y  nt3: bh1.z/w
            mma16816(acc[0][0], acc[0][1], acc[0][2], acc[0][3], ah0, ah1, ah2, ah3, bh0.x, bh0.y);
            mma16816(acc[1][0], acc[1][1], acc[1][2], acc[1][3], ah0, ah1, ah2, ah3, bh0.z, bh0.w);
            mma16816(acc[2][0], acc[2][1], acc[2][2], acc[2][3], ah0, ah1, ah2, ah3, bh1.x, bh1.y);
            mma16816(acc[3][0], acc[3][1], acc[3][2], acc[3][3], ah0, ah1, ah2, ah3, bh1.z, bh1.w);

            mma16816(acc[0][0], acc[0][1], acc[0][2], acc[0][3], ah0, ah1, ah2, ah3, bl0.x, bl0.y);
            mma16816(acc[1][0], acc[1][1], acc[1][2], acc[1][3], ah0, ah1, ah2, ah3, bl0.z, bl0.w);
            mma16816(acc[2][0], acc[2][1], acc[2][2], acc[2][3], ah0, ah1, ah2, ah3, bl1.x, bl1.y);
            mma16816(acc[3][0], acc[3][1], acc[3][2], acc[3][3], ah0, ah1, ah2, ah3, bl1.z, bl1.w);

            mma16816(acc[0][0], acc[0][1], acc[0][2], acc[0][3], al0, al1, al2, al3, bh0.x, bh0.y);
            mma16816(acc[1][0], acc[1][1], acc[1][2], acc[1][3], al0, al1, al2, al3, bh0.z, bh0.w);
            mma16816(acc[2][0], acc[2][1], acc[2][2], acc[2][3], al0, al1, al2, al3, bh1.x, bh1.y);
            mma16816(acc[3][0], acc[3][1], acc[3][2], acc[3][3], al0, al1, al2, al3, bh1.z, bh1.w);
        }

        // ---- epilogue: c0,c1 = (px g4, co 2t4/2t4+1); c2,c3 = px g4+8 ----
        #pragma unroll
        for (int nt = 0; nt < 4; ++nt) {
            const size_t co0 = (size_t)(nt * 8 + 2 * t4) * 16384;
            og[co0 + w0 + g4]             = acc[nt][0] + bias_lo[nt];
            og[co0 + 16384 + w0 + g4]     = acc[nt][1] + bias_hi[nt];
            og[co0 + w0 + g4 + 8]         = acc[nt][2] + bias_lo[nt];
            og[co0 + 16384 + w0 + g4 + 8] = acc[nt][3] + bias_hi[nt];
        }
    }
}

extern "C" void kernel_launch(void* const* d_in, const int* in_sizes, int n_in,
                              void* d_out, int out_size)
{
    const float* x = (const float*)d_in[0];
    const float* w = (const float*)d_in[1];
    const float* b = (const float*)d_in[2];
    float* out = (float*)d_out;

    cudaFuncSetAttribute(grouped_conv_hmma,
                         cudaFuncAttributeMaxDynamicSharedMemorySize, SMEM_TOTAL);

    dim3 grid(32, 256);   // 4-row h blocks, n*16+g
    grouped_conv_hmma<<<grid, THREADS, SMEM_TOTAL>>>(x, w, b, out);
}

// round 5
// speedup vs baseline: 1.7513x; 1.0682x over previous
#include <cuda_runtime.h>
#include <cuda_bf16.h>
#include <cstdint>

// Grouped conv2d via implicit GEMM on mma.sync (HMMA), split-bf16 3-pass.
// x[16,256,128,128] * W[512,16,3,3] (groups=16) + b -> out[16,512,128,128]
// R5: taps-outer loop, B fragments hoisted to registers (LDS traffic halved).

#define THREADS 256

// ---- smem layout (bytes) ----
#define SWF_OFF   0
#define SWF_BYTES (18 * 32 * 48)            // B frags [combo][lane][12 u32]
#define XCOL_STRIDE 36
#define XROW_STRIDE (130 * XCOL_STRIDE)     // 4680
#define XPLANE_BYTES (6 * XROW_STRIDE)      // 28080
#define SXH_OFF   SWF_BYTES
#define SXL_OFF   (SXH_OFF + XPLANE_BYTES)
#define SBIAS_OFF (SXL_OFF + XPLANE_BYTES)
#define SMEM_TOTAL (SBIAS_OFF + 128)        // 83936

__device__ __forceinline__ void mma16816(float& c0, float& c1, float& c2, float& c3,
                                         uint32_t a0, uint32_t a1, uint32_t a2, uint32_t a3,
                                         uint32_t b0, uint32_t b1) {
    asm volatile("mma.sync.aligned.m16n8k16.row.col.f32.bf16.bf16.f32 "
                 "{%0,%1,%2,%3}, {%4,%5,%6,%7}, {%8,%9}, {%0,%1,%2,%3};"
                 : "+f"(c0), "+f"(c1), "+f"(c2), "+f"(c3)
                 : "r"(a0), "r"(a1), "r"(a2), "r"(a3), "r"(b0), "r"(b1));
}

__device__ __forceinline__ uint32_t bf16_hi_lo_pack(float v0, float v1, int want_lo) {
    __nv_bfloat16 h0 = __float2bfloat16(v0);
    __nv_bfloat16 h1 = __float2bfloat16(v1);
    __nv_bfloat16 e0, e1;
    if (want_lo) {
        e0 = __float2bfloat16(v0 - __bfloat162float(h0));
        e1 = __float2bfloat16(v1 - __bfloat162float(h1));
    } else {
        e0 = h0; e1 = h1;
    }
    return (uint32_t)__bfloat16_as_ushort(e0) | ((uint32_t)__bfloat16_as_ushort(e1) << 16);
}

__global__ __launch_bounds__(THREADS, 2)
void grouped_conv_hmma(const float* __restrict__ x,
                       const float* __restrict__ w,
                       const float* __restrict__ bias,
                       float* __restrict__ out)
{
    extern __shared__ char smem[];
    uint32_t* swf = (uint32_t*)(smem + SWF_OFF);
    char* sxh = smem + SXH_OFF;
    char* sxl = smem + SXL_OFF;
    float* sbias = (float*)(smem + SBIAS_OFF);

    const int tid = threadIdx.x;
    const int wid = tid >> 5;
    const int lane = tid & 31;

    const int hb = blockIdx.x;          // 0..31  (4-row blocks)
    const int ng = blockIdx.y;          // 0..255
    const int n  = ng >> 4;
    const int g  = ng & 15;
    const int h0 = hb * 4;

    // ---- stage x: rows h0-1..h0+4, cols -1..128, split bf16 hi/lo (ci pairs) ----
    const float* xg = x + (size_t)(n * 256 + g * 16) * 16384;
    for (int idx = tid; idx < 6 * 8 * 130; idx += THREADS) {
        int c   = idx % 130;
        int t   = idx / 130;
        int ci2 = t % 8;                // ci pair
        int r   = t / 8;                // 0..5
        int gh = h0 - 1 + r;
        int gw = c - 1;
        float v0 = 0.0f, v1 = 0.0f;
        if ((unsigned)gh < 128u && (unsigned)gw < 128u) {
            const float* p = xg + (ci2 * 2) * 16384 + gh * 128 + gw;
            v0 = p[0];
            v1 = p[16384];
        }
        uint32_t off = (uint32_t)(r * XROW_STRIDE + c * XCOL_STRIDE + ci2 * 4);
        *(uint32_t*)(sxh + off) = bf16_hi_lo_pack(v0, v1, 0);
        *(uint32_t*)(sxl + off) = bf16_hi_lo_pack(v0, v1, 1);
    }

    // ---- stage W as ready-made B fragments ----
    const float* wgp = w + (size_t)(g * 32) * 144;
    for (int idx = tid; idx < 18 * 32 * 8; idx += THREADS) {
        int slot  = idx & 7;
        int lane2 = (idx >> 3) & 31;
        int combo = idx >> 8;           // 0..17
        int tap = combo >> 1, hl = combo & 1;
        int g4 = lane2 >> 2, t4 = lane2 & 3;
        int nt = slot >> 1, rr = slot & 1;
        int co  = nt * 8 + g4;
        int ci0 = 2 * t4 + 8 * rr;
        float v0 = wgp[co * 144 + ci0 * 9 + tap];
        float v1 = wgp[co * 144 + (ci0 + 1) * 9 + tap];
        swf[(combo * 32 + lane2) * 12 + slot] = bf16_hi_lo_pack(v0, v1, hl);
    }
    if (tid < 32) sbias[tid] = bias[g * 32 + tid];
    __syncthreads();

    // ---- main: warp = (row, w-half); taps outer, 4 segments inner ----
    const int wrow  = wid >> 1;          // 0..3
    const int whalf = (wid & 1) * 64;
    const int g4 = lane >> 2, t4 = lane & 3;
    const int h = h0 + wrow;
    float* og = out + (size_t)(n * 512 + g * 32) * 16384 + (size_t)h * 128;

    float acc[4][4][4];                  // [seg][nt][4]
    #pragma unroll
    for (int s = 0; s < 4; ++s)
        #pragma unroll
        for (int nt = 0; nt < 4; ++nt)
            #pragma unroll
            for (int i = 0; i < 4; ++i) acc[s][nt][i] = 0.0f;

    #pragma unroll
    for (int tap = 0; tap < 9; ++tap) {
        const int dh = tap / 3, dw = tap % 3;
        // B fragments for this tap (hi, lo) -> registers, reused across 4 segs
        const uint32_t* bp = swf + (tap * 2 * 32 + lane) * 12;
        uint4 bh0 = *(const uint4*)(bp);
        uint4 bh1 = *(const uint4*)(bp + 4);
        uint4 bl0 = *(const uint4*)(bp + 12 * 32);
        uint4 bl1 = *(const uint4*)(bp + 12 * 32 + 4);

        #pragma unroll
        for (int seg = 0; seg < 4; ++seg) {
            const int w0 = whalf + seg * 16;
            const uint32_t abase = (uint32_t)((wrow + dh) * XROW_STRIDE
                                            + (w0 + dw) * XCOL_STRIDE + t4 * 4);
            uint32_t ah0 = *(const uint32_t*)(sxh + abase + g4 * XCOL_STRIDE);
            uint32_t ah1 = *(const uint32_t*)(sxh + abase + (g4 + 8) * XCOL_STRIDE);
            uint32_t ah2 = *(const uint32_t*)(sxh + abase + g4 * XCOL_STRIDE + 16);
            uint32_t ah3 = *(const uint32_t*)(sxh + abase + (g4 + 8) * XCOL_STRIDE + 16);
            uint32_t al0 = *(const uint32_t*)(sxl + abase + g4 * XCOL_STRIDE);
            uint32_t al1 = *(const uint32_t*)(sxl + abase + (g4 + 8) * XCOL_STRIDE);
            uint32_t al2 = *(const uint32_t*)(sxl + abase + g4 * XCOL_STRIDE + 16);
            uint32_t al3 = *(const uint32_t*)(sxl + abase + (g4 + 8) * XCOL_STRIDE + 16);

            float* a0 = acc[seg][0];
            float* a1 = acc[seg][1];
            float* a2 = acc[seg][2];
            float* a3 = acc[seg][3];

            mma16816(a0[0], a0[1], a0[2], a0[3], ah0, ah1, ah2, ah3, bh0.x, bh0.y);
            mma16816(a1[0], a1[1], a1[2], a1[3], ah0, ah1, ah2, ah3, bh0.z, bh0.w);
            mma16816(a2[0], a2[1], a2[2], a2[3], ah0, ah1, ah2, ah3, bh1.x, bh1.y);
            mma16816(a3[0], a3[1], a3[2], a3[3], ah0, ah1, ah2, ah3, bh1.z, bh1.w);

            mma16816(a0[0], a0[1], a0[2], a0[3], ah0, ah1, ah2, ah3, bl0.x, bl0.y);
            mma16816(a1[0], a1[1], a1[2], a1[3], ah0, ah1, ah2, ah3, bl0.z, bl0.w);
            mma16816(a2[0], a2[1], a2[2], a2[3], ah0, ah1, ah2, ah3, bl1.x, bl1.y);
            mma16816(a3[0], a3[1], a3[2], a3[3], ah0, ah1, ah2, ah3, bl1.z, bl1.w);

            mma16816(a0[0], a0[1], a0[2], a0[3], al0, al1, al2, al3, bh0.x, bh0.y);
            mma16816(a1[0], a1[1], a1[2], a1[3], al0, al1, al2, al3, bh0.z, bh0.w);
            mma16816(a2[0], a2[1], a2[2], a2[3], al0, al1, al2, al3, bh1.x, bh1.y);
            mma16816(a3[0], a3[1], a3[2], a3[3], al0, al1, al2, al3, bh1.z, bh1.w);
        }
    }

    // ---- epilogue ----
    float bias_lo[4], bias_hi[4];
    #pragma unroll
    for (int nt = 0; nt < 4; ++nt) {
        bias_lo[nt] = sbias[nt * 8 + 2 * t4];
        bias_hi[nt] = sbias[nt * 8 + 2 * t4 + 1];
    }
    #pragma unroll
    for (int seg = 0; seg < 4; ++seg) {
        const int w0 = whalf + seg * 16;
        #pragma unroll
        for (int nt = 0; nt < 4; ++nt) {
            const size_t co0 = (size_t)(nt * 8 + 2 * t4) * 16384;
            og[co0 + w0 + g4]             = acc[seg][nt][0] + bias_lo[nt];
            og[co0 + 16384 + w0 + g4]     = acc[seg][nt][1] + bias_hi[nt];
            og[co0 + w0 + g4 + 8]         = acc[seg][nt][2] + bias_lo[nt];
            og[co0 + 16384 + w0 + g4 + 8] = acc[seg][nt][3] + bias_hi[nt];
        }
    }
}

extern "C" void kernel_launch(void* const* d_in, const int* in_sizes, int n_in,
                              void* d_out, int out_size)
{
    const float* x = (const float*)d_in[0];
    const float* w = (const float*)d_in[1];
    const float* b = (const float*)d_in[2];
    float* out = (float*)d_out;

    cudaFuncSetAttribute(grouped_conv_hmma,
                         cudaFuncAttributeMaxDynamicSharedMemorySize, SMEM_TOTAL);

    dim3 grid(32, 256);   // 4-row h blocks, n*16+g
    grouped_conv_hmma<<<grid, THREADS, SMEM_TOTAL>>>(x, w, b, out);
}